// round 4
// baseline (speedup 1.0000x reference)
#include <cuda_runtime.h>
#include <math.h>

// Fixed problem dims (from reference)
#define HH   256
#define NHH  8
#define HDD  32
#define CC   100
#define NMAX 262144

// ---------------- device scratch (no allocations allowed) ----------------
__device__ __align__(16) float g_wqk[NHH * HH];
__device__ float g_qb[NHH];
__device__ int   g_counts[CC];
__device__ int   g_offsets[CC + 1];
__device__ int   g_cursor[CC];
__device__ int   g_sorted[NMAX];
__device__ __align__(16) float g_A[CC * NHH * HH];   // 800KB
__device__ float g_den[CC * NHH];
__device__ __align__(16) float g_x[CC * HH];
__device__ __align__(16) float g_qkv[CC * 3 * HH];
__device__ __align__(16) float g_attn[CC * HH];
__device__ __align__(16) float g_ff[CC * 4 * HH];

// ---------------- helpers ----------------
__device__ __forceinline__ unsigned long long fma2(unsigned long long a,
                                                   unsigned long long b,
                                                   unsigned long long c) {
    unsigned long long d;
    asm("fma.rn.f32x2 %0, %1, %2, %3;" : "=l"(d) : "l"(a), "l"(b), "l"(c));
    return d;
}
__device__ __forceinline__ unsigned long long pk2(float lo, float hi) {
    unsigned long long r;
    asm("mov.b64 %0, {%1, %2};" : "=l"(r) : "f"(lo), "f"(hi));
    return r;
}
__device__ __forceinline__ void upk2(unsigned long long v, float& lo, float& hi) {
    asm("mov.b64 {%0, %1}, %2;" : "=f"(lo), "=f"(hi) : "l"(v));
}

// 256-length dot: warp-cooperative, weight row from global (coalesced float4),
// activations from shared. Result valid in all lanes.
__device__ __forceinline__ float warp_dot256(const float* __restrict__ w, const float* sh) {
    int l = threadIdx.x & 31;
    float4 wa = *(const float4*)(w + 4 * l);
    float4 wb = *(const float4*)(w + 128 + 4 * l);
    float4 xa = *(const float4*)(sh + 4 * l);
    float4 xb = *(const float4*)(sh + 128 + 4 * l);
    float s = wa.x * xa.x + wa.y * xa.y + wa.z * xa.z + wa.w * xa.w
            + wb.x * xb.x + wb.y * xb.y + wb.z * xb.z + wb.w * xb.w;
#pragma unroll
    for (int off = 16; off > 0; off >>= 1) s += __shfl_xor_sync(0xffffffffu, s, off);
    return s;
}

__device__ __forceinline__ float warp_dot1024(const float* __restrict__ w, const float* sh) {
    int l = threadIdx.x & 31;
    float s = 0.f;
#pragma unroll
    for (int k = 0; k < 8; k++) {
        float4 a = *(const float4*)(w + 128 * k + 4 * l);
        float4 b = *(const float4*)(sh + 128 * k + 4 * l);
        s += a.x * b.x + a.y * b.y + a.z * b.z + a.w * b.w;
    }
#pragma unroll
    for (int off = 16; off > 0; off >>= 1) s += __shfl_xor_sync(0xffffffffu, s, off);
    return s;
}

// LayerNorm over 256 values (one per thread in a 256-thread block).
__device__ __forceinline__ float block_ln_256(float v, float gg, float bb, float* red) {
    int t = threadIdx.x, lane = t & 31, w = t >> 5;
    float s = v, q = v * v;
#pragma unroll
    for (int off = 16; off > 0; off >>= 1) {
        s += __shfl_xor_sync(0xffffffffu, s, off);
        q += __shfl_xor_sync(0xffffffffu, q, off);
    }
    if (lane == 0) { red[w] = s; red[8 + w] = q; }
    __syncthreads();
    float S = 0.f, Q = 0.f;
#pragma unroll
    for (int i = 0; i < 8; i++) { S += red[i]; Q += red[8 + i]; }
    float mu  = S * (1.0f / 256.0f);
    float var = Q * (1.0f / 256.0f) - mu * mu;
    return (v - mu) * rsqrtf(var + 1e-5f) * gg + bb;
}

__device__ __forceinline__ float gelu_exact(float v) {
    return 0.5f * v * (1.0f + erff(v * 0.70710678118654752f));
}

// ---------------- kernels ----------------
__global__ void k_init() {
    int i = blockIdx.x * blockDim.x + threadIdx.x;
    int st = gridDim.x * blockDim.x;
    for (int j = i; j < CC * NHH * HH; j += st) g_A[j] = 0.f;
    for (int j = i; j < CC * NHH; j += st) g_den[j] = 0.f;
    if (i < CC) { g_counts[i] = 0; g_cursor[i] = 0; }
}

// wqk[h,i] = scale * sum_d q[h,d]*k_w[h*32+d, i];  qb[h] = scale * sum_d q[h,d]*k_b[h*32+d]
__global__ void k_wqk(const float* __restrict__ q, const float* __restrict__ kw,
                      const float* __restrict__ kb) {
    const float scale = 0.17677669529663687f;  // 32^-0.5
    int h = blockIdx.x, i = threadIdx.x;
    float acc = 0.f;
#pragma unroll 8
    for (int d = 0; d < HDD; d++) acc += q[h * HDD + d] * kw[(h * HDD + d) * HH + i];
    g_wqk[h * HH + i] = acc * scale;
    if (i == 0) {
        float b = 0.f;
        for (int d = 0; d < HDD; d++) b += q[h * HDD + d] * kb[h * HDD + d];
        g_qb[h] = b * scale;
    }
}

__global__ void k_hist(const int* __restrict__ ci, int n) {
    __shared__ int sh[CC];
    for (int t = threadIdx.x; t < CC; t += blockDim.x) sh[t] = 0;
    __syncthreads();
    for (int i = blockIdx.x * blockDim.x + threadIdx.x; i < n; i += gridDim.x * blockDim.x)
        atomicAdd(&sh[ci[i]], 1);
    __syncthreads();
    for (int t = threadIdx.x; t < CC; t += blockDim.x) atomicAdd(&g_counts[t], sh[t]);
}

__global__ void k_scan() {
    if (threadIdx.x == 0) {
        int s = 0;
        for (int c = 0; c < CC; c++) { g_offsets[c] = s; s += g_counts[c]; }
        g_offsets[CC] = s;
    }
}

__global__ void k_scatter(const int* __restrict__ ci, int n) {
    for (int i = blockIdx.x * blockDim.x + threadIdx.x; i < n; i += gridDim.x * blockDim.x) {
        int c = ci[i];
        int pos = g_offsets[c] + atomicAdd(&g_cursor[c], 1);
        g_sorted[pos] = i;
    }
}

// Main single-pass: scores = x@wqk^T, e = exp(score), A[c] += e*x, den[c] += e.
// grid (CC, 8), 256 threads. Each warp owns a full A-partial in registers (f32x2).
__global__ void __launch_bounds__(256) k_main(const float* __restrict__ X) {
    int c = blockIdx.x;
    int warp = threadIdx.x >> 5;
    int lane = threadIdx.x & 31;
    int wg = blockIdx.y * 8 + warp;  // 0..63
    int start = g_offsets[c], end = g_offsets[c + 1];

    unsigned long long w2[8][4];
    float qbv[8];
#pragma unroll
    for (int h = 0; h < 8; h++) {
        qbv[h] = g_qb[h];
#pragma unroll
        for (int k = 0; k < 4; k++)
            w2[h][k] = *(const unsigned long long*)(g_wqk + h * 256 + k * 64 + 2 * lane);
    }
    unsigned long long a2[8][4];
#pragma unroll
    for (int h = 0; h < 8; h++)
#pragma unroll
        for (int k = 0; k < 4; k++) a2[h][k] = 0ull;  // bits of (0.f,0.f)
    float dacc[8];
#pragma unroll
    for (int h = 0; h < 8; h++) dacc[h] = 0.f;

    for (int i = start + wg; i < end; i += 64) {
        int n = g_sorted[i];
        const float* row = X + (size_t)n * 256;
        unsigned long long x2[4];
#pragma unroll
        for (int k = 0; k < 4; k++)
            x2[k] = *(const unsigned long long*)(row + k * 64 + 2 * lane);
        // per-lane score partials (8 heads), packed FMA
        float p[8];
#pragma unroll
        for (int h = 0; h < 8; h++) {
            unsigned long long acc = fma2(x2[0], w2[h][0], 0ull);
            acc = fma2(x2[1], w2[h][1], acc);
            acc = fma2(x2[2], w2[h][2], acc);
            acc = fma2(x2[3], w2[h][3], acc);
            float lo, hi; upk2(acc, lo, hi);
            p[h] = lo + hi;
        }
#pragma unroll
        for (int off = 16; off > 0; off >>= 1)
#pragma unroll
            for (int h = 0; h < 8; h++) p[h] += __shfl_xor_sync(0xffffffffu, p[h], off);
        float e[8];
#pragma unroll
        for (int h = 0; h < 8; h++) {
            e[h] = __expf(p[h] + qbv[h]);  // |score| ~ 2 -> no max shift needed
            dacc[h] += e[h];
        }
#pragma unroll
        for (int h = 0; h < 8; h++) {
            unsigned long long e2 = pk2(e[h], e[h]);
            a2[h][0] = fma2(e2, x2[0], a2[h][0]);
            a2[h][1] = fma2(e2, x2[1], a2[h][1]);
            a2[h][2] = fma2(e2, x2[2], a2[h][2]);
            a2[h][3] = fma2(e2, x2[3], a2[h][3]);
        }
    }
    // merge warp partials into global A / den
#pragma unroll
    for (int h = 0; h < 8; h++)
#pragma unroll
        for (int k = 0; k < 4; k++) {
            float lo, hi; upk2(a2[h][k], lo, hi);
            float* dst = &g_A[(c * 8 + h) * 256 + k * 64 + 2 * lane];
            atomicAdd(dst, lo);
            atomicAdd(dst + 1, hi);
        }
    if (lane == 0)
#pragma unroll
        for (int h = 0; h < 8; h++) atomicAdd(&g_den[c * 8 + h], dacc[h]);
}

// pooled[c,h,d] = (A[c,h,:]·v_w[h*32+d,:])/den + v_b;  emb = LN(pooled @ po_w^T + po_b)
__global__ void __launch_bounds__(256) k_pool(const float* __restrict__ vw,
                                              const float* __restrict__ vb,
                                              const float* __restrict__ pw,
                                              const float* __restrict__ pb,
                                              const float* __restrict__ png,
                                              const float* __restrict__ pnb) {
    int c = blockIdx.x, t = threadIdx.x, warp = t >> 5, lane = t & 31;
    __shared__ __align__(16) float shA[2048];
    __shared__ __align__(16) float shP[256];
    __shared__ float shO[256];
    __shared__ float shden[8];
    __shared__ float red[16];
#pragma unroll
    for (int j = 0; j < 8; j++) shA[t + 256 * j] = g_A[c * 2048 + t + 256 * j];
    if (t < 8) shden[t] = g_den[c * 8 + t];
    __syncthreads();
    int h = warp;
    float den = shden[h];
    float rden = den > 0.f ? 1.f / den : 0.f;
    for (int d = 0; d < 32; d++) {
        float num = warp_dot256(vw + (h * 32 + d) * 256, shA + h * 256);
        float pooled = (den > 0.f) ? (num * rden + vb[h * 32 + d]) : 0.f;
        if (lane == 0) shP[h * 32 + d] = pooled;
    }
    __syncthreads();
    for (int d = 0; d < 32; d++) {
        int j = warp * 32 + d;
        float o = warp_dot256(pw + j * 256, shP) + pb[j];
        if (lane == 0) shO[j] = o;
    }
    __syncthreads();
    float v = shO[t];
    float r = block_ln_256(v, png[t], pnb[t], red);
    g_x[c * 256 + t] = (g_counts[c] > 0) ? r : 0.f;
}

__global__ void __launch_bounds__(256) k_qkv(const float* __restrict__ W,
                                             const float* __restrict__ B) {
    int c = blockIdx.x, t = threadIdx.x, warp = t >> 5, lane = t & 31;
    __shared__ __align__(16) float shx[256];
    shx[t] = g_x[c * 256 + t];
    __syncthreads();
    for (int j = warp; j < 768; j += 8) {
        float o = warp_dot256(W + j * 256, shx) + B[j];
        if (lane == 0) g_qkv[c * 768 + j] = o;
    }
}

__global__ void __launch_bounds__(256) k_attn() {
    int c = blockIdx.x, t = threadIdx.x, h = t >> 5, lane = t & 31;
    __shared__ __align__(16) float shq[256];
    __shared__ float she[8][128];
    shq[t] = g_qkv[c * 768 + t];
    __syncthreads();
    const float scale = 0.17677669529663687f;
    float sc[4];
#pragma unroll
    for (int r = 0; r < 4; r++) {
        int m = lane + 32 * r;
        if (m < CC) {
            const float* kk = g_qkv + m * 768 + 256 + h * 32;
            const float* qq = shq + h * 32;
            float s = 0.f;
#pragma unroll
            for (int kx = 0; kx < 8; kx++) {
                float4 a = *(const float4*)(kk + 4 * kx);
                float4 b = *(const float4*)(qq + 4 * kx);
                s += a.x * b.x + a.y * b.y + a.z * b.z + a.w * b.w;
            }
            sc[r] = s * scale;
        } else sc[r] = -3.0e38f;
    }
    float M = fmaxf(fmaxf(sc[0], sc[1]), fmaxf(sc[2], sc[3]));
#pragma unroll
    for (int off = 16; off > 0; off >>= 1) M = fmaxf(M, __shfl_xor_sync(0xffffffffu, M, off));
    float sum = 0.f;
#pragma unroll
    for (int r = 0; r < 4; r++) {
        int m = lane + 32 * r;
        float e = (m < CC) ? __expf(sc[r] - M) : 0.f;
        if (m < CC) she[h][m] = e;
        sum += e;
    }
#pragma unroll
    for (int off = 16; off > 0; off >>= 1) sum += __shfl_xor_sync(0xffffffffu, sum, off);
    __syncwarp();
    float inv = 1.f / sum;
    float acc = 0.f;
#pragma unroll 4
    for (int m = 0; m < CC; m++)
        acc += she[h][m] * g_qkv[m * 768 + 512 + h * 32 + lane];
    g_attn[c * 256 + h * 32 + lane] = acc * inv;
}

__global__ void __launch_bounds__(256) k_oln(const float* __restrict__ W,
                                             const float* __restrict__ B,
                                             const float* __restrict__ gg,
                                             const float* __restrict__ bb) {
    int c = blockIdx.x, t = threadIdx.x, warp = t >> 5, lane = t & 31;
    __shared__ __align__(16) float shin[256];
    __shared__ float sho[256];
    __shared__ float red[16];
    shin[t] = g_attn[c * 256 + t];
    __syncthreads();
    for (int d = 0; d < 32; d++) {
        int j = warp * 32 + d;
        float o = warp_dot256(W + j * 256, shin) + B[j];
        if (lane == 0) sho[j] = o;
    }
    __syncthreads();
    float v = g_x[c * 256 + t] + sho[t];
    float r = block_ln_256(v, gg[t], bb[t], red);
    g_x[c * 256 + t] = r;
}

__global__ void __launch_bounds__(256) k_ff1(const float* __restrict__ W,
                                             const float* __restrict__ B) {
    int c = blockIdx.x, t = threadIdx.x, warp = t >> 5, lane = t & 31;
    __shared__ __align__(16) float shx[256];
    shx[t] = g_x[c * 256 + t];
    __syncthreads();
    for (int j = warp; j < 1024; j += 8) {
        float v = warp_dot256(W + j * 256, shx) + B[j];
        if (lane == 0) g_ff[c * 1024 + j] = gelu_exact(v);
    }
}

__global__ void __launch_bounds__(256) k_ff2(const float* __restrict__ W,
                                             const float* __restrict__ B,
                                             const float* __restrict__ gg,
                                             const float* __restrict__ bb) {
    int c = blockIdx.x, t = threadIdx.x, warp = t >> 5, lane = t & 31;
    __shared__ __align__(16) float shf[1024];
    __shared__ float sho[256];
    __shared__ float red[16];
#pragma unroll
    for (int j = 0; j < 4; j++) shf[t + 256 * j] = g_ff[c * 1024 + t + 256 * j];
    __syncthreads();
    for (int d = 0; d < 32; d++) {
        int j = warp * 32 + d;
        float o = warp_dot1024(W + j * 1024, shf) + B[j];
        if (lane == 0) sho[j] = o;
    }
    __syncthreads();
    float v = g_x[c * 256 + t] + sho[t];
    float r = block_ln_256(v, gg[t], bb[t], red);
    g_x[c * 256 + t] = r;
}

__global__ void __launch_bounds__(256) k_head(const float* __restrict__ r1w,
                                              const float* __restrict__ r1b,
                                              const float* __restrict__ r2w,
                                              const float* __restrict__ r2b,
                                              float* __restrict__ out) {
    int c = blockIdx.x, t = threadIdx.x, warp = t >> 5, lane = t & 31;
    __shared__ __align__(16) float shx[256];
    __shared__ float shh[128];
    shx[t] = g_x[c * 256 + t];
    __syncthreads();
    for (int j = warp; j < 128; j += 8) {
        float v = warp_dot256(r1w + j * 256, shx) + r1b[j];
        if (lane == 0) shh[j] = gelu_exact(v);
    }
    __syncthreads();
    if (warp == 0) {
        float s = 0.f;
#pragma unroll
        for (int r = 0; r < 4; r++) s += shh[lane + 32 * r] * r2w[lane + 32 * r];
#pragma unroll
        for (int off = 16; off > 0; off >>= 1) s += __shfl_xor_sync(0xffffffffu, s, off);
        if (lane == 0) out[c] = s + r2b[0];
    }
}

// ---------------- launch ----------------
extern "C" void kernel_launch(void* const* d_in, const int* in_sizes, int n_in,
                              void* d_out, int out_size) {
    const float* x    = (const float*)d_in[0];
    const int*   ci   = (const int*)d_in[1];
    const float* q    = (const float*)d_in[3];
    const float* kw   = (const float*)d_in[4];
    const float* kb   = (const float*)d_in[5];
    const float* vw   = (const float*)d_in[6];
    const float* vb   = (const float*)d_in[7];
    const float* pw   = (const float*)d_in[8];
    const float* pb   = (const float*)d_in[9];
    const float* png  = (const float*)d_in[10];
    const float* pnb  = (const float*)d_in[11];
    const float* tinw = (const float*)d_in[12];
    const float* tinb = (const float*)d_in[13];
    const float* totw = (const float*)d_in[14];
    const float* totb = (const float*)d_in[15];
    const float* ln1g = (const float*)d_in[16];
    const float* ln1b = (const float*)d_in[17];
    const float* ff1w = (const float*)d_in[18];
    const float* ff1b = (const float*)d_in[19];
    const float* ff2w = (const float*)d_in[20];
    const float* ff2b = (const float*)d_in[21];
    const float* ln2g = (const float*)d_in[22];
    const float* ln2b = (const float*)d_in[23];
    const float* r1w  = (const float*)d_in[24];
    const float* r1b  = (const float*)d_in[25];
    const float* r2w  = (const float*)d_in[26];
    const float* r2b  = (const float*)d_in[27];
    float* out = (float*)d_out;
    int n = in_sizes[0] / HH;

    k_init<<<256, 256>>>();
    k_wqk<<<8, 256>>>(q, kw, kb);
    k_hist<<<256, 256>>>(ci, n);
    k_scan<<<1, 32>>>();
    k_scatter<<<256, 256>>>(ci, n);
    k_main<<<dim3(CC, 8), 256>>>(x);
    k_pool<<<CC, 256>>>(vw, vb, pw, pb, png, pnb);
    for (int l = 0; l < 2; l++) {
        k_qkv<<<CC, 256>>>(tinw + (size_t)l * 768 * 256, tinb + l * 768);
        k_attn<<<CC, 256>>>();
        k_oln<<<CC, 256>>>(totw + (size_t)l * 256 * 256, totb + l * 256,
                           ln1g + l * 256, ln1b + l * 256);
        k_ff1<<<CC, 256>>>(ff1w + (size_t)l * 1024 * 256, ff1b + l * 1024);
        k_ff2<<<CC, 256>>>(ff2w + (size_t)l * 256 * 1024, ff2b + l * 256,
                           ln2g + l * 256, ln2b + l * 256);
    }
    k_head<<<CC, 256>>>(r1w, r1b, r2w, r2b, out);
}

// round 5
// speedup vs baseline: 2.0413x; 2.0413x over previous
#include <cuda_runtime.h>
#include <math.h>

#define HH   256
#define NHH  8
#define HDD  32
#define CC   100
#define NMAX 262144
#define BY   4            // partial blocks per commit in k_main

typedef unsigned long long ull;

// ---------------- device scratch ----------------
__device__ __align__(16) float g_wqk[NHH * HH];
__device__ float g_qb[NHH];
__device__ int   g_counts[CC];
__device__ int   g_offsets[CC + 1];
__device__ int   g_cursor[CC];
__device__ int   g_sorted[NMAX];
__device__ __align__(16) float g_Apart[CC * BY * NHH * HH];   // 3.3MB partials
__device__ float g_denpart[CC * BY * NHH];
__device__ __align__(16) float g_x[CC * HH];
__device__ __align__(16) float g_qkv[CC * 3 * HH];
__device__ __align__(16) float g_ff[CC * 4 * HH];

// ---------------- helpers ----------------
__device__ __forceinline__ ull fma2(ull a, ull b, ull c) {
    ull d;
    asm("fma.rn.f32x2 %0, %1, %2, %3;" : "=l"(d) : "l"(a), "l"(b), "l"(c));
    return d;
}
__device__ __forceinline__ ull pk2(float lo, float hi) {
    ull r; asm("mov.b64 %0, {%1, %2};" : "=l"(r) : "f"(lo), "f"(hi)); return r;
}
__device__ __forceinline__ void upk2(ull v, float& lo, float& hi) {
    asm("mov.b64 {%0, %1}, %2;" : "=f"(lo), "=f"(hi) : "l"(v));
}

__device__ __forceinline__ float block_ln_256(float v, float gg, float bb, float* red) {
    int t = threadIdx.x, lane = t & 31, w = t >> 5;
    float s = v, q = v * v;
#pragma unroll
    for (int off = 16; off > 0; off >>= 1) {
        s += __shfl_xor_sync(0xffffffffu, s, off);
        q += __shfl_xor_sync(0xffffffffu, q, off);
    }
    if (lane == 0) { red[w] = s; red[8 + w] = q; }
    __syncthreads();
    float S = 0.f, Q = 0.f;
#pragma unroll
    for (int i = 0; i < 8; i++) { S += red[i]; Q += red[8 + i]; }
    float mu  = S * (1.0f / 256.0f);
    float var = Q * (1.0f / 256.0f) - mu * mu;
    return (v - mu) * rsqrtf(var + 1e-5f) * gg + bb;
}

__device__ __forceinline__ float gelu_exact(float v) {
    return 0.5f * v * (1.0f + erff(v * 0.70710678118654752f));
}

// ---------------- kernels ----------------
__global__ void k_init_counts() { int t = threadIdx.x; if (t < CC) g_counts[t] = 0; }
__global__ void k_init_cursor() { int t = threadIdx.x; if (t < CC) g_cursor[t] = 0; }

__global__ void k_wqk(const float* __restrict__ q, const float* __restrict__ kw,
                      const float* __restrict__ kb) {
    const float scale = 0.17677669529663687f;
    int h = blockIdx.x, i = threadIdx.x;
    float acc = 0.f;
#pragma unroll 8
    for (int d = 0; d < HDD; d++) acc += q[h * HDD + d] * kw[(h * HDD + d) * HH + i];
    g_wqk[h * HH + i] = acc * scale;
    if (i == 0) {
        float b = 0.f;
        for (int d = 0; d < HDD; d++) b += q[h * HDD + d] * kb[h * HDD + d];
        g_qb[h] = b * scale;
    }
}

__global__ void k_hist(const int* __restrict__ ci, int n) {
    __shared__ int sh[CC];
    for (int t = threadIdx.x; t < CC; t += blockDim.x) sh[t] = 0;
    __syncthreads();
    for (int i = blockIdx.x * blockDim.x + threadIdx.x; i < n; i += gridDim.x * blockDim.x)
        atomicAdd(&sh[ci[i]], 1);
    __syncthreads();
    for (int t = threadIdx.x; t < CC; t += blockDim.x) atomicAdd(&g_counts[t], sh[t]);
}

// Scan (per-block, deterministic) + per-block range reservation + local scatter.
__global__ void __launch_bounds__(256) k_scatter(const int* __restrict__ ci, int n) {
    __shared__ int soff[CC + 1], scnt[CC], sbase[CC], scur[CC];
    int t = threadIdx.x;
    for (int j = t; j < CC; j += 256) { scnt[j] = 0; scur[j] = 0; }
    __syncthreads();
    int per = (n + gridDim.x - 1) / gridDim.x;
    int lo = blockIdx.x * per;
    int hi = min(n, lo + per);
    for (int i = lo + t; i < hi; i += 256) atomicAdd(&scnt[ci[i]], 1);
    __syncthreads();
    if (t == 0) {
        int s = 0;
        for (int c = 0; c < CC; c++) { soff[c] = s; s += g_counts[c]; }
        soff[CC] = s;
        if (blockIdx.x == 0)
            for (int c = 0; c <= CC; c++) g_offsets[c] = soff[c];
    }
    __syncthreads();
    if (t < CC) sbase[t] = soff[t] + atomicAdd(&g_cursor[t], scnt[t]);
    __syncthreads();
    for (int i = lo + t; i < hi; i += 256) {
        int c = ci[i];
        int p = sbase[c] + atomicAdd(&scur[c], 1);
        g_sorted[p] = i;
    }
}

// Main single pass: scores + exp + segmented weighted-sum of rows.
// grid (CC, BY), 256 threads. Register accumulators, block tree-reduce, NO atomics.
__global__ void __launch_bounds__(256) k_main(const float* __restrict__ X) {
    __shared__ ull sred[4][1024];   // 32KB cross-warp reduction staging
    __shared__ float sden[8][8];
    int c = blockIdx.x;
    int warp = threadIdx.x >> 5;
    int lane = threadIdx.x & 31;
    int wg = blockIdx.y * 8 + warp;        // 0..31
    const int stride = BY * 8;             // 32
    int start = g_offsets[c], end = g_offsets[c + 1];

    ull w2[8][4];
    float qbv[8];
#pragma unroll
    for (int h = 0; h < 8; h++) {
        qbv[h] = g_qb[h];
#pragma unroll
        for (int k = 0; k < 4; k++)
            w2[h][k] = *(const ull*)(g_wqk + h * 256 + k * 64 + 2 * lane);
    }
    ull a2[8][4];
#pragma unroll
    for (int h = 0; h < 8; h++)
#pragma unroll
        for (int k = 0; k < 4; k++) a2[h][k] = 0ull;
    float dacc[8];
#pragma unroll
    for (int h = 0; h < 8; h++) dacc[h] = 0.f;

    int i = start + wg;
    if (i < end) {
        int n_cur = g_sorted[i];
        const ull* row = (const ull*)(X + (size_t)n_cur * 256);
        ull xc[4];
#pragma unroll
        for (int k = 0; k < 4; k++) xc[k] = __ldcs(row + k * 32 + lane);
        while (i < end) {
            int inext = i + stride;
            int n_nxt = (inext < end) ? g_sorted[inext] : n_cur;
            const ull* rown = (const ull*)(X + (size_t)n_nxt * 256);
            ull xn[4];
#pragma unroll
            for (int k = 0; k < 4; k++) xn[k] = __ldcs(rown + k * 32 + lane);

            // scores (packed fma)
            float p[8];
#pragma unroll
            for (int h = 0; h < 8; h++) {
                ull acc = fma2(xc[0], w2[h][0], 0ull);
                acc = fma2(xc[1], w2[h][1], acc);
                acc = fma2(xc[2], w2[h][2], acc);
                acc = fma2(xc[3], w2[h][3], acc);
                float lo, hi; upk2(acc, lo, hi);
                p[h] = lo + hi;
            }
#pragma unroll
            for (int off = 16; off > 0; off >>= 1)
#pragma unroll
                for (int h = 0; h < 8; h++)
                    p[h] += __shfl_xor_sync(0xffffffffu, p[h], off);
#pragma unroll
            for (int h = 0; h < 8; h++) {
                float e = __expf(p[h] + qbv[h]);   // |score| ~ 2, no max shift needed
                dacc[h] += e;
                ull e2 = pk2(e, e);
                a2[h][0] = fma2(e2, xc[0], a2[h][0]);
                a2[h][1] = fma2(e2, xc[1], a2[h][1]);
                a2[h][2] = fma2(e2, xc[2], a2[h][2]);
                a2[h][3] = fma2(e2, xc[3], a2[h][3]);
            }
#pragma unroll
            for (int k = 0; k < 4; k++) xc[k] = xn[k];
            i = inext; n_cur = n_nxt;
        }
    }

    // den: warp-uniform -> shared
    if (lane == 0)
#pragma unroll
        for (int h = 0; h < 8; h++) sden[warp][h] = dacc[h];

    // cross-warp tree reduce of a2 (8 -> 4 -> 2 -> 1)
    if (warp >= 4)
#pragma unroll
        for (int h = 0; h < 8; h++)
#pragma unroll
            for (int k = 0; k < 4; k++) sred[warp - 4][h * 128 + k * 32 + lane] = a2[h][k];
    __syncthreads();
    if (warp < 4)
#pragma unroll
        for (int h = 0; h < 8; h++)
#pragma unroll
            for (int k = 0; k < 4; k++) {
                float alo, ahi, blo, bhi;
                upk2(a2[h][k], alo, ahi);
                upk2(sred[warp][h * 128 + k * 32 + lane], blo, bhi);
                a2[h][k] = pk2(alo + blo, ahi + bhi);
            }
    __syncthreads();
    if (warp >= 2 && warp < 4)
#pragma unroll
        for (int h = 0; h < 8; h++)
#pragma unroll
            for (int k = 0; k < 4; k++) sred[warp - 2][h * 128 + k * 32 + lane] = a2[h][k];
    __syncthreads();
    if (warp < 2)
#pragma unroll
        for (int h = 0; h < 8; h++)
#pragma unroll
            for (int k = 0; k < 4; k++) {
                float alo, ahi, blo, bhi;
                upk2(a2[h][k], alo, ahi);
                upk2(sred[warp][h * 128 + k * 32 + lane], blo, bhi);
                a2[h][k] = pk2(alo + blo, ahi + bhi);
            }
    __syncthreads();
    if (warp == 1)
#pragma unroll
        for (int h = 0; h < 8; h++)
#pragma unroll
            for (int k = 0; k < 4; k++) sred[0][h * 128 + k * 32 + lane] = a2[h][k];
    __syncthreads();
    if (warp == 0) {
        ull* dst = (ull*)(g_Apart + (size_t)(c * BY + blockIdx.y) * 2048);
#pragma unroll
        for (int h = 0; h < 8; h++)
#pragma unroll
            for (int k = 0; k < 4; k++) {
                float alo, ahi, blo, bhi;
                upk2(a2[h][k], alo, ahi);
                upk2(sred[0][h * 128 + k * 32 + lane], blo, bhi);
                dst[h * 128 + k * 32 + lane] = pk2(alo + blo, ahi + bhi);
            }
        if (lane < 8) {
            float d = 0.f;
#pragma unroll
            for (int w = 0; w < 8; w++) d += sden[w][lane];
            g_denpart[(c * BY + blockIdx.y) * 8 + lane] = d;
        }
    }
}

// pooled = (A·v_w^T)/den + v_b; emb = LN(pooled @ po_w^T + po_b); gate empty commits.
__global__ void __launch_bounds__(256) k_pool(const float* __restrict__ vw,
                                              const float* __restrict__ vb,
                                              const float* __restrict__ pw,
                                              const float* __restrict__ pb,
                                              const float* __restrict__ png,
                                              const float* __restrict__ pnb) {
    int c = blockIdx.x, t = threadIdx.x, warp = t >> 5, lane = t & 31;
    __shared__ __align__(16) float shA[2048];
    __shared__ __align__(16) float shP[256];
    __shared__ float shO[256];
    __shared__ float shden[8];
    __shared__ float red[16];
#pragma unroll
    for (int j = 0; j < 8; j++) {
        float s = 0.f;
#pragma unroll
        for (int p = 0; p < BY; p++)
            s += g_Apart[(size_t)(c * BY + p) * 2048 + t + 256 * j];
        shA[t + 256 * j] = s;
    }
    if (t < 8) {
        float d = 0.f;
#pragma unroll
        for (int p = 0; p < BY; p++) d += g_denpart[(c * BY + p) * 8 + t];
        shden[t] = d;
    }
    __syncthreads();
    int h = warp;
    float den = shden[h];
    float rden = den > 0.f ? 1.f / den : 0.f;
    for (int d = 0; d < 32; d++) {
        const float* w = vw + (h * 32 + d) * 256;
        float4 wa = *(const float4*)(w + 4 * lane);
        float4 wb = *(const float4*)(w + 128 + 4 * lane);
        float4 xa = *(const float4*)(shA + h * 256 + 4 * lane);
        float4 xb = *(const float4*)(shA + h * 256 + 128 + 4 * lane);
        float s = wa.x * xa.x + wa.y * xa.y + wa.z * xa.z + wa.w * xa.w
                + wb.x * xb.x + wb.y * xb.y + wb.z * xb.z + wb.w * xb.w;
#pragma unroll
        for (int off = 16; off > 0; off >>= 1) s += __shfl_xor_sync(0xffffffffu, s, off);
        if (lane == 0)
            shP[h * 32 + d] = (den > 0.f) ? (s * rden + vb[h * 32 + d]) : 0.f;
    }
    __syncthreads();
    for (int d = 0; d < 32; d++) {
        int j = warp * 32 + d;
        const float* w = pw + j * 256;
        float4 wa = *(const float4*)(w + 4 * lane);
        float4 wb = *(const float4*)(w + 128 + 4 * lane);
        float4 xa = *(const float4*)(shP + 4 * lane);
        float4 xb = *(const float4*)(shP + 128 + 4 * lane);
        float s = wa.x * xa.x + wa.y * xa.y + wa.z * xa.z + wa.w * xa.w
                + wb.x * xb.x + wb.y * xb.y + wb.z * xb.z + wb.w * xb.w;
#pragma unroll
        for (int off = 16; off > 0; off >>= 1) s += __shfl_xor_sync(0xffffffffu, s, off);
        if (lane == 0) shO[j] = s + pb[j];
    }
    __syncthreads();
    float r = block_ln_256(shO[t], png[t], pnb[t], red);
    g_x[c * 256 + t] = (g_counts[c] > 0) ? r : 0.f;
}

// qkv projection, 4 commits per block, 256-row slice per blockIdx.y (3 slices).
__global__ void __launch_bounds__(256) k_qkv(const float* __restrict__ W,
                                             const float* __restrict__ B) {
    int cbase = blockIdx.x * 4, t = threadIdx.x, warp = t >> 5, lane = t & 31;
    int jbase = blockIdx.y * 256;
    __shared__ __align__(16) float shx[4][256];
#pragma unroll
    for (int cc = 0; cc < 4; cc++)
        shx[cc][t] = g_x[(cbase + cc) * 256 + t];
    __syncthreads();
    for (int r = 0; r < 32; r++) {
        int j = jbase + warp * 32 + r;
        const float* w = W + (size_t)j * 256;
        float4 wa = *(const float4*)(w + 4 * lane);
        float4 wb = *(const float4*)(w + 128 + 4 * lane);
        float s[4];
#pragma unroll
        for (int cc = 0; cc < 4; cc++) {
            float4 xa = *(const float4*)(&shx[cc][4 * lane]);
            float4 xb = *(const float4*)(&shx[cc][128 + 4 * lane]);
            s[cc] = wa.x * xa.x + wa.y * xa.y + wa.z * xa.z + wa.w * xa.w
                  + wb.x * xb.x + wb.y * xb.y + wb.z * xb.z + wb.w * xb.w;
        }
#pragma unroll
        for (int off = 16; off > 0; off >>= 1)
#pragma unroll
            for (int cc = 0; cc < 4; cc++)
                s[cc] += __shfl_xor_sync(0xffffffffu, s[cc], off);
        if (lane == 0) {
            float bj = B[j];
#pragma unroll
            for (int cc = 0; cc < 4; cc++)
                g_qkv[(cbase + cc) * 768 + j] = s[cc] + bj;
        }
    }
}

// attention over commits + output projection + residual + LN, fused per-commit.
__global__ void __launch_bounds__(256) k_attn_oln(const float* __restrict__ W,
                                                  const float* __restrict__ B,
                                                  const float* __restrict__ gg,
                                                  const float* __restrict__ bb) {
    int c = blockIdx.x, t = threadIdx.x, h = t >> 5, lane = t & 31;
    __shared__ __align__(16) float shq[256];
    __shared__ float she[8][128];
    __shared__ float satt[256];
    __shared__ float sho[256];
    __shared__ float red[16];
    shq[t] = g_qkv[c * 768 + t];
    __syncthreads();
    const float scale = 0.17677669529663687f;
    float sc[4];
#pragma unroll
    for (int r = 0; r < 4; r++) {
        int m = lane + 32 * r;
        if (m < CC) {
            const float* kk = g_qkv + m * 768 + 256 + h * 32;
            const float* qq = shq + h * 32;
            float s = 0.f;
#pragma unroll
            for (int kx = 0; kx < 8; kx++) {
                float4 a = *(const float4*)(kk + 4 * kx);
                float4 b = *(const float4*)(qq + 4 * kx);
                s += a.x * b.x + a.y * b.y + a.z * b.z + a.w * b.w;
            }
            sc[r] = s * scale;
        } else sc[r] = -3.0e38f;
    }
    float M = fmaxf(fmaxf(sc[0], sc[1]), fmaxf(sc[2], sc[3]));
#pragma unroll
    for (int off = 16; off > 0; off >>= 1) M = fmaxf(M, __shfl_xor_sync(0xffffffffu, M, off));
    float sum = 0.f;
#pragma unroll
    for (int r = 0; r < 4; r++) {
        int m = lane + 32 * r;
        float e = (m < CC) ? __expf(sc[r] - M) : 0.f;
        if (m < CC) she[h][m] = e;
        sum += e;
    }
#pragma unroll
    for (int off = 16; off > 0; off >>= 1) sum += __shfl_xor_sync(0xffffffffu, sum, off);
    __syncwarp();
    float inv = 1.f / sum;
    float acc = 0.f;
#pragma unroll 4
    for (int m = 0; m < CC; m++)
        acc += she[h][m] * g_qkv[m * 768 + 512 + h * 32 + lane];
    satt[h * 32 + lane] = acc * inv;
    __syncthreads();
    // output projection
    for (int d = 0; d < 32; d++) {
        int j = h * 32 + d;
        const float* w = W + (size_t)j * 256;
        float4 wa = *(const float4*)(w + 4 * lane);
        float4 wb = *(const float4*)(w + 128 + 4 * lane);
        float4 xa = *(const float4*)(satt + 4 * lane);
        float4 xb = *(const float4*)(satt + 128 + 4 * lane);
        float s = wa.x * xa.x + wa.y * xa.y + wa.z * xa.z + wa.w * xa.w
                + wb.x * xb.x + wb.y * xb.y + wb.z * xb.z + wb.w * xb.w;
#pragma unroll
        for (int off = 16; off > 0; off >>= 1) s += __shfl_xor_sync(0xffffffffu, s, off);
        if (lane == 0) sho[j] = s;
    }
    __syncthreads();
    float v = g_x[c * 256 + t] + sho[t] + B[t];
    float r = block_ln_256(v, gg[t], bb[t], red);
    g_x[c * 256 + t] = r;
}

// ff1 + gelu, 4 commits per block, 256-row slice per blockIdx.y (4 slices).
__global__ void __launch_bounds__(256) k_ff1(const float* __restrict__ W,
                                             const float* __restrict__ B) {
    int cbase = blockIdx.x * 4, t = threadIdx.x, warp = t >> 5, lane = t & 31;
    int jbase = blockIdx.y * 256;
    __shared__ __align__(16) float shx[4][256];
#pragma unroll
    for (int cc = 0; cc < 4; cc++)
        shx[cc][t] = g_x[(cbase + cc) * 256 + t];
    __syncthreads();
    for (int r = 0; r < 32; r++) {
        int j = jbase + warp * 32 + r;
        const float* w = W + (size_t)j * 256;
        float4 wa = *(const float4*)(w + 4 * lane);
        float4 wb = *(const float4*)(w + 128 + 4 * lane);
        float s[4];
#pragma unroll
        for (int cc = 0; cc < 4; cc++) {
            float4 xa = *(const float4*)(&shx[cc][4 * lane]);
            float4 xb = *(const float4*)(&shx[cc][128 + 4 * lane]);
            s[cc] = wa.x * xa.x + wa.y * xa.y + wa.z * xa.z + wa.w * xa.w
                  + wb.x * xb.x + wb.y * xb.y + wb.z * xb.z + wb.w * xb.w;
        }
#pragma unroll
        for (int off = 16; off > 0; off >>= 1)
#pragma unroll
            for (int cc = 0; cc < 4; cc++)
                s[cc] += __shfl_xor_sync(0xffffffffu, s[cc], off);
        if (lane == 0) {
            float bj = B[j];
#pragma unroll
            for (int cc = 0; cc < 4; cc++)
                g_ff[(cbase + cc) * 1024 + j] = gelu_exact(s[cc] + bj);
        }
    }
}

// ff2 + residual + LN, 4 commits per block.
__global__ void __launch_bounds__(256) k_ff2(const float* __restrict__ W,
                                             const float* __restrict__ B,
                                             const float* __restrict__ gg,
                                             const float* __restrict__ bb) {
    int cbase = blockIdx.x * 4, t = threadIdx.x, warp = t >> 5, lane = t & 31;
    __shared__ __align__(16) float shf[4][1024];
    __shared__ float sho[4][256];
    __shared__ float red[16];
#pragma unroll
    for (int cc = 0; cc < 4; cc++)
        for (int idx = t; idx < 1024; idx += 256)
            shf[cc][idx] = g_ff[(cbase + cc) * 1024 + idx];
    __syncthreads();
    for (int r = 0; r < 32; r++) {
        int j = warp * 32 + r;
        const float4* wr = (const float4*)(W + (size_t)j * 1024);
        float4 wreg[8];
#pragma unroll
        for (int q = 0; q < 8; q++) wreg[q] = wr[q * 32 + lane];
        float s[4];
#pragma unroll
        for (int cc = 0; cc < 4; cc++) {
            float acc = 0.f;
#pragma unroll
            for (int q = 0; q < 8; q++) {
                float4 x = *(const float4*)(&shf[cc][q * 128 + 4 * lane]);
                acc += wreg[q].x * x.x + wreg[q].y * x.y + wreg[q].z * x.z + wreg[q].w * x.w;
            }
            s[cc] = acc;
        }
#pragma unroll
        for (int off = 16; off > 0; off >>= 1)
#pragma unroll
            for (int cc = 0; cc < 4; cc++)
                s[cc] += __shfl_xor_sync(0xffffffffu, s[cc], off);
        if (lane == 0) {
            float bj = B[j];
#pragma unroll
            for (int cc = 0; cc < 4; cc++) sho[cc][j] = s[cc] + bj;
        }
    }
    __syncthreads();
#pragma unroll
    for (int cc = 0; cc < 4; cc++) {
        int c = cbase + cc;
        float v = g_x[c * 256 + t] + sho[cc][t];
        float r = block_ln_256(v, gg[t], bb[t], red);
        g_x[c * 256 + t] = r;
        __syncthreads();
    }
}

// ranking head, 4 commits per block.
__global__ void __launch_bounds__(256) k_head(const float* __restrict__ r1w,
                                              const float* __restrict__ r1b,
                                              const float* __restrict__ r2w,
                                              const float* __restrict__ r2b,
                                              float* __restrict__ out) {
    int cbase = blockIdx.x * 4, t = threadIdx.x, warp = t >> 5, lane = t & 31;
    __shared__ __align__(16) float shx[4][256];
    __shared__ float shh[4][128];
#pragma unroll
    for (int cc = 0; cc < 4; cc++)
        shx[cc][t] = g_x[(cbase + cc) * 256 + t];
    __syncthreads();
    for (int r = 0; r < 16; r++) {
        int j = warp * 16 + r;
        const float* w = r1w + (size_t)j * 256;
        float4 wa = *(const float4*)(w + 4 * lane);
        float4 wb = *(const float4*)(w + 128 + 4 * lane);
        float s[4];
#pragma unroll
        for (int cc = 0; cc < 4; cc++) {
            float4 xa = *(const float4*)(&shx[cc][4 * lane]);
            float4 xb = *(const float4*)(&shx[cc][128 + 4 * lane]);
            s[cc] = wa.x * xa.x + wa.y * xa.y + wa.z * xa.z + wa.w * xa.w
                  + wb.x * xb.x + wb.y * xb.y + wb.z * xb.z + wb.w * xb.w;
        }
#pragma unroll
        for (int off = 16; off > 0; off >>= 1)
#pragma unroll
            for (int cc = 0; cc < 4; cc++)
                s[cc] += __shfl_xor_sync(0xffffffffu, s[cc], off);
        if (lane == 0) {
            float bj = r1b[j];
#pragma unroll
            for (int cc = 0; cc < 4; cc++)
                shh[cc][j] = gelu_exact(s[cc] + bj);
        }
    }
    __syncthreads();
    if (warp < 4) {
        float s = 0.f;
#pragma unroll
        for (int r = 0; r < 4; r++)
            s += shh[warp][lane + 32 * r] * r2w[lane + 32 * r];
#pragma unroll
        for (int off = 16; off > 0; off >>= 1) s += __shfl_xor_sync(0xffffffffu, s, off);
        if (lane == 0) out[cbase + warp] = s + r2b[0];
    }
}

// ---------------- launch ----------------
extern "C" void kernel_launch(void* const* d_in, const int* in_sizes, int n_in,
                              void* d_out, int out_size) {
    const float* x    = (const float*)d_in[0];
    const int*   ci   = (const int*)d_in[1];
    const float* q    = (const float*)d_in[3];
    const float* kw   = (const float*)d_in[4];
    const float* kb   = (const float*)d_in[5];
    const float* vw   = (const float*)d_in[6];
    const float* vb   = (const float*)d_in[7];
    const float* pw   = (const float*)d_in[8];
    const float* pb   = (const float*)d_in[9];
    const float* png  = (const float*)d_in[10];
    const float* pnb  = (const float*)d_in[11];
    const float* tinw = (const float*)d_in[12];
    const float* tinb = (const float*)d_in[13];
    const float* totw = (const float*)d_in[14];
    const float* totb = (const float*)d_in[15];
    const float* ln1g = (const float*)d_in[16];
    const float* ln1b = (const float*)d_in[17];
    const float* ff1w = (const float*)d_in[18];
    const float* ff1b = (const float*)d_in[19];
    const float* ff2w = (const float*)d_in[20];
    const float* ff2b = (const float*)d_in[21];
    const float* ln2g = (const float*)d_in[22];
    const float* ln2b = (const float*)d_in[23];
    const float* r1w  = (const float*)d_in[24];
    const float* r1b  = (const float*)d_in[25];
    const float* r2w  = (const float*)d_in[26];
    const float* r2b  = (const float*)d_in[27];
    float* out = (float*)d_out;
    int n = in_sizes[0] / HH;

    k_init_counts<<<1, 128>>>();          // launch 1
    k_init_cursor<<<1, 128>>>();          // launch 2
    k_wqk<<<8, 256>>>(q, kw, kb);         // launch 3
    k_hist<<<256, 256>>>(ci, n);          // launch 4
    k_scatter<<<256, 256>>>(ci, n);       // launch 5
    k_main<<<dim3(CC, BY), 256>>>(x);     // launch 6 (ncu -s 5 captures this)
    k_pool<<<CC, 256>>>(vw, vb, pw, pb, png, pnb);
    for (int l = 0; l < 2; l++) {
        k_qkv<<<dim3(25, 3), 256>>>(tinw + (size_t)l * 768 * 256, tinb + l * 768);
        k_attn_oln<<<CC, 256>>>(totw + (size_t)l * 256 * 256, totb + l * 256,
                                ln1g + l * 256, ln1b + l * 256);
        k_ff1<<<dim3(25, 4), 256>>>(ff1w + (size_t)l * 1024 * 256, ff1b + l * 1024);
        k_ff2<<<25, 256>>>(ff2w + (size_t)l * 256 * 1024, ff2b + l * 256,
                           ln2g + l * 256, ln2b + l * 256);
    }
    k_head<<<25, 256>>>(r1w, r1b, r2w, r2b, out);
}